// round 5
// baseline (speedup 1.0000x reference)
#include <cuda_runtime.h>
#include <cuda_bf16.h>
#include <cuda_fp16.h>
#include <math.h>
#include <stdint.h>

#define BB 8
#define CC 512
#define HS 1024
#define KP 144
#define NO 9
#define HW 196

// ---------------- scratch (device globals; zero-initialized) ---------------
__device__ __align__(16) __nv_bfloat16 g_x3 [BB * HW * 1536];   // [(b,hw)][1536] = [Xh,Xh,Xl]
__device__ __align__(16) __nv_bfloat16 g_w13[HS * 1536];        // [h][1536]      = [Wh,Wl,Wh]
__device__ __align__(16) __nv_bfloat16 g_w23[HS * 1536];
// fp16 2-term projections for cofe: cp2 rows: [cph 0..143 | 0 | cpl 160..303 | 0]
__device__ __align__(16) __half g_cp2[BB * 320 * HS];           // [b][320][i]
__device__ __align__(16) __half g_sp2[NO * BB * 160 * HS];      // [o*8+b][160][j] (rows 144..159 zero)

// ---------------- asm helpers ----------------------------------------------
__device__ __forceinline__ uint32_t smem_u32(const void* p) {
    uint32_t a;
    asm("{ .reg .u64 t; cvta.to.shared.u64 t, %1; cvt.u32.u64 %0, t; }" : "=r"(a) : "l"(p));
    return a;
}
__device__ __forceinline__ void cp16(uint32_t s, const void* g) {
    asm volatile("cp.async.cg.shared.global [%0], [%1], 16;" :: "r"(s), "l"(g));
}
__device__ __forceinline__ void cpcommit() { asm volatile("cp.async.commit_group;" ::: "memory"); }
__device__ __forceinline__ void cpwait0() { asm volatile("cp.async.wait_group 0;" ::: "memory"); }
__device__ __forceinline__ void cpwait1() { asm volatile("cp.async.wait_group 1;" ::: "memory"); }

__device__ __forceinline__ void ldsm4(uint32_t* r, uint32_t a) {
    asm volatile("ldmatrix.sync.aligned.m8n8.x4.shared.b16 {%0,%1,%2,%3}, [%4];"
                 : "=r"(r[0]), "=r"(r[1]), "=r"(r[2]), "=r"(r[3]) : "r"(a));
}
__device__ __forceinline__ void ldsm4t(uint32_t* r, uint32_t a) {
    asm volatile("ldmatrix.sync.aligned.m8n8.x4.trans.shared.b16 {%0,%1,%2,%3}, [%4];"
                 : "=r"(r[0]), "=r"(r[1]), "=r"(r[2]), "=r"(r[3]) : "r"(a));
}
__device__ __forceinline__ void mma_bf16(float* c, const uint32_t* a, const uint32_t* b) {
    asm volatile(
        "mma.sync.aligned.m16n8k16.row.col.f32.bf16.bf16.f32 "
        "{%0,%1,%2,%3},{%4,%5,%6,%7},{%8,%9},{%0,%1,%2,%3};"
        : "+f"(c[0]), "+f"(c[1]), "+f"(c[2]), "+f"(c[3])
        : "r"(a[0]), "r"(a[1]), "r"(a[2]), "r"(a[3]), "r"(b[0]), "r"(b[1]));
}
__device__ __forceinline__ void mma_f16(float* c, const uint32_t* a, const uint32_t* b) {
    asm volatile(
        "mma.sync.aligned.m16n8k16.row.col.f32.f16.f16.f32 "
        "{%0,%1,%2,%3},{%4,%5,%6,%7},{%8,%9},{%0,%1,%2,%3};"
        : "+f"(c[0]), "+f"(c[1]), "+f"(c[2]), "+f"(c[3])
        : "r"(a[0]), "r"(a[1]), "r"(a[2]), "r"(a[3]), "r"(b[0]), "r"(b[1]));
}

// ---------------- convert kernels ------------------------------------------
__global__ void conv_w3(const float* __restrict__ w1, const float* __restrict__ w2) {
    int i = blockIdx.x * 256 + threadIdx.x;
    const float* s = blockIdx.y ? w2 : w1;
    __nv_bfloat16* d = blockIdx.y ? g_w23 : g_w13;
    int h = i >> 9, c = i & 511;
    float v = s[i];
    __nv_bfloat16 hv = __float2bfloat16(v);
    __nv_bfloat16 lv = __float2bfloat16(v - __bfloat162float(hv));
    int base = h * 1536 + c;
    d[base] = hv; d[base + 512] = lv; d[base + 1024] = hv;
}

__global__ void conv_x3(const float* __restrict__ x) {
    __shared__ float t[32][33];
    int b = blockIdx.z, hw0 = blockIdx.y * 32, c0 = blockIdx.x * 32;
    for (int i = threadIdx.y; i < 32; i += 8) {
        int hw = hw0 + threadIdx.x;
        t[i][threadIdx.x] = (hw < HW) ? x[((size_t)b * CC + c0 + i) * HW + hw] : 0.f;
    }
    __syncthreads();
    for (int i = threadIdx.y; i < 32; i += 8) {
        int hw = hw0 + i, c = c0 + threadIdx.x;
        if (hw < HW) {
            float v = t[threadIdx.x][i];
            __nv_bfloat16 hv = __float2bfloat16(v);
            __nv_bfloat16 lv = __float2bfloat16(v - __bfloat162float(hv));
            size_t base = ((size_t)b * HW + hw) * 1536 + c;
            g_x3[base] = hv; g_x3[base + 512] = hv; g_x3[base + 1024] = lv;
        }
    }
}

// ---------------- projection GEMM (bf16 3-term, K'=1536) --------------------
#define PROJ_SMEM 40960
__global__ void __launch_bounds__(256, 2) proj_kernel(const float* __restrict__ b1,
                                                      const float* __restrict__ b2) {
    extern __shared__ char smraw[];
    __shared__ int soff[128];
    __shared__ int doff[128];
    const uint32_t sb = smem_u32(smraw);
    const int tid = threadIdx.x, wid = tid >> 5, l = tid & 31;

    const int h0 = blockIdx.x * 128;
    const int r0 = blockIdx.y * 128;
    const int o = r0 / (BB * KP);
    const int rem0 = r0 - o * (BB * KP);
    const int dy = (o == NO) ? 0 : (o / 3 - 1);
    const int dx = (o == NO) ? 0 : (o % 3 - 1);

    if (tid < 128) {
        int rr = rem0 + tid;
        int b = rr / KP, k = rr - b * KP;
        int yy = 1 + k / 12 + dy, xx = 1 + k % 12 + dx;
        soff[tid] = (b * HW + yy * 14 + xx) * 1536;
        doff[tid] = (((o == NO) ? (b * 320) : ((o * BB + b) * 160)) + k) * 1024;
    }
    const __nv_bfloat16* W = (o == NO) ? g_w13 : g_w23;
    const float* bias = (o == NO) ? b1 : b2;
    __syncthreads();

    const uint32_t Ab[2] = {sb, sb + 10240};
    const uint32_t Bb[2] = {sb + 20480, sb + 30720};

    const int Wm = (wid >> 1) * 32, Wn = (wid & 1) * 64;
    const int aRow = (l & 15), aKb = (l >> 4) * 16;
    const int bN = (l & 7) + (l >> 4) * 8, bKb = ((l >> 3) & 1) * 16;

    float acc[2][8][4] = {};

    {
        #pragma unroll
        for (int i = 0; i < 2; i++) {
            int c = tid + i * 256, row = c >> 2, kc = c & 3;
            cp16(Ab[0] + row * 80 + kc * 16, g_x3 + soff[row] + kc * 8);
        }
        #pragma unroll
        for (int i = 0; i < 2; i++) {
            int c = tid + i * 256, row = c >> 2, kc = c & 3;
            cp16(Bb[0] + row * 80 + kc * 16, W + (size_t)(h0 + row) * 1536 + kc * 8);
        }
        cpcommit();
    }

    for (int it = 0; it < 48; ++it) {
        const int buf = it & 1;
        if (it + 1 < 48) {
            const int c0 = (it + 1) * 32, nb = buf ^ 1;
            #pragma unroll
            for (int i = 0; i < 2; i++) {
                int c = tid + i * 256, row = c >> 2, kc = c & 3;
                cp16(Ab[nb] + row * 80 + kc * 16, g_x3 + soff[row] + c0 + kc * 8);
            }
            #pragma unroll
            for (int i = 0; i < 2; i++) {
                int c = tid + i * 256, row = c >> 2, kc = c & 3;
                cp16(Bb[nb] + row * 80 + kc * 16, W + (size_t)(h0 + row) * 1536 + c0 + kc * 8);
            }
            cpcommit();
            cpwait1();
        } else {
            cpwait0();
        }
        __syncthreads();
        #pragma unroll
        for (int s = 0; s < 2; s++) {
            uint32_t a[2][4], bb[4][4];
            #pragma unroll
            for (int t = 0; t < 2; t++)
                ldsm4(a[t], Ab[buf] + (Wm + t * 16 + aRow) * 80 + s * 32 + aKb);
            #pragma unroll
            for (int p = 0; p < 4; p++)
                ldsm4(bb[p], Bb[buf] + (Wn + p * 16 + bN) * 80 + s * 32 + bKb);
            #pragma unroll
            for (int mt = 0; mt < 2; mt++)
                #pragma unroll
                for (int nt = 0; nt < 8; nt++)
                    mma_bf16(acc[mt][nt], a[mt], &bb[nt >> 1][(nt & 1) * 2]);
        }
        __syncthreads();
    }

    // epilogue: stage, add bias, fp16 split, store (cp: hi+lo; sp: hi only)
    float* stage = (float*)smraw;
    for (int half = 0; half < 2; ++half) {
        __syncthreads();
        if ((wid >> 2) == half) {
            int rbase = Wm - half * 64;
            #pragma unroll
            for (int mt = 0; mt < 2; mt++)
                #pragma unroll
                for (int nt = 0; nt < 8; nt++) {
                    int row = rbase + mt * 16 + (l >> 2);
                    int col = Wn + nt * 8 + 2 * (l & 3);
                    stage[row * 132 + col]           = acc[mt][nt][0];
                    stage[row * 132 + col + 1]       = acc[mt][nt][1];
                    stage[(row + 8) * 132 + col]     = acc[mt][nt][2];
                    stage[(row + 8) * 132 + col + 1] = acc[mt][nt][3];
                }
        }
        __syncthreads();
        for (int idx = tid; idx < 8192; idx += 256) {
            int m = idx >> 7, h = idx & 127;
            float v = stage[m * 132 + h] + bias[h0 + h];
            __half hv = __float2half_rn(v);
            int dbase = doff[half * 64 + m] + h0 + h;
            if (o == NO) {
                __half lv = __float2half_rn(v - __half2float(hv));
                g_cp2[dbase] = hv;
                g_cp2[dbase + 160 * 1024] = lv;
            } else {
                g_sp2[dbase] = hv;
            }
        }
    }
}

// ---------------- fused cofe GEMM + normalization ---------------------------
// C[i][j] = sum cp2[b][k][i]*sp2[ob][k mod 160][j]; K'=320 (A halves share B)
// A panel resident: 320 x 528B = 168960; B: 3 x 32x272B = 26112; sumsq/scale
#define COFE_SMEM (168960 + 26112 + 1024 + 1024)
__global__ void __launch_bounds__(256, 1) cofe_kernel(float* __restrict__ out) {
    extern __shared__ char smraw[];
    const uint32_t sb = smem_u32(smraw);
    const uint32_t Abase = sb;
    const uint32_t Bbase = sb + 168960;
    float* sumsq = (float*)(smraw + 168960 + 26112);
    float* scale = (float*)(smraw + 168960 + 26112 + 1024);

    const int tid = threadIdx.x, wid = tid >> 5, l = tid & 31;
    const int i0 = blockIdx.x * 256;
    const int p = blockIdx.y, b = p / NO, o = p - b * NO;

    const __half* Ag = g_cp2 + (size_t)b * 320 * 1024 + i0;
    const __half* Bg = g_sp2 + (size_t)(o * BB + b) * 160 * 1024;

    sumsq[tid] = 0.f;

    // A panel: 320 rows x 512B
    for (int idx = tid; idx < 320 * 32; idx += 256) {
        int k = idx >> 5, ic = idx & 31;
        cp16(Abase + k * 528 + ic * 16, Ag + (size_t)k * 1024 + ic * 8);
    }
    // B chunk 0 (group 0, with A), chunk 1 (group 1)
    #pragma unroll
    for (int i = 0; i < 2; i++) {
        int idx = tid + i * 256, kr = idx >> 4, jc = idx & 15;
        cp16(Bbase + kr * 272 + jc * 16, Bg + (size_t)kr * 1024 + jc * 8);
    }
    cpcommit();
    #pragma unroll
    for (int i = 0; i < 2; i++) {
        int idx = tid + i * 256, kr = idx >> 4, jc = idx & 15;
        cp16(Bbase + 8704 + kr * 272 + jc * 16, Bg + (size_t)(32 + kr) * 1024 + jc * 8);
    }
    cpcommit();

    const int Wm = (wid >> 1) * 64, Wn = (wid & 1) * 64;
    const int aK = (l & 7) + (l >> 4) * 8, aI = ((l >> 3) & 1) * 8;
    const int bK = (l & 7) + ((l >> 3) & 1) * 8, bJ = (l >> 4) * 8;

    float acc[4][8][4] = {};
    float* outp = out + (size_t)p * HS * HS;

    for (int g = 0; g < 40; ++g) {
        const int jt = g / 5, c = g % 5, buf = g % 3;
        if (g < 39) cpwait1(); else cpwait0();
        __syncthreads();
        if (g + 2 < 40) {
            const int g2 = g + 2, jt2 = g2 / 5, c2 = g2 % 5, buf2 = g2 % 3;
            #pragma unroll
            for (int i = 0; i < 2; i++) {
                int idx = tid + i * 256, kr = idx >> 4, jc = idx & 15;
                cp16(Bbase + buf2 * 8704 + kr * 272 + jc * 16,
                     Bg + (size_t)(c2 * 32 + kr) * 1024 + jt2 * 128 + jc * 8);
            }
            cpcommit();
        }
        #pragma unroll
        for (int s = 0; s < 2; s++) {
            uint32_t bb[4][4];
            #pragma unroll
            for (int q = 0; q < 4; q++)
                ldsm4t(bb[q], Bbase + buf * 8704 + (s * 16 + bK) * 272 + (Wn + q * 16 + bJ) * 2);
            #pragma unroll
            for (int half = 0; half < 2; half++) {
                uint32_t a[4][4];
                const int krow = half * 160 + c * 32 + s * 16 + aK;
                #pragma unroll
                for (int t = 0; t < 4; t++)
                    ldsm4t(a[t], Abase + krow * 528 + (Wm + t * 16 + aI) * 2);
                #pragma unroll
                for (int mt = 0; mt < 4; mt++)
                    #pragma unroll
                    for (int nt = 0; nt < 8; nt++)
                        mma_f16(acc[mt][nt], a[mt], &bb[nt >> 1][(nt & 1) * 2]);
            }
        }
        if (c == 4) {
            // epilogue for j-tile jt: store unnormalized + accumulate sumsq
            #pragma unroll
            for (int mt = 0; mt < 4; mt++) {
                const int lr = Wm + mt * 16 + (l >> 2);
                float s1 = 0.f, s2 = 0.f;
                #pragma unroll
                for (int nt = 0; nt < 8; nt++) {
                    int gj = jt * 128 + Wn + nt * 8 + 2 * (l & 3);
                    *reinterpret_cast<float2*>(outp + (size_t)(i0 + lr) * HS + gj) =
                        make_float2(acc[mt][nt][0], acc[mt][nt][1]);
                    *reinterpret_cast<float2*>(outp + (size_t)(i0 + lr + 8) * HS + gj) =
                        make_float2(acc[mt][nt][2], acc[mt][nt][3]);
                    s1 += acc[mt][nt][0] * acc[mt][nt][0] + acc[mt][nt][1] * acc[mt][nt][1];
                    s2 += acc[mt][nt][2] * acc[mt][nt][2] + acc[mt][nt][3] * acc[mt][nt][3];
                    acc[mt][nt][0] = acc[mt][nt][1] = acc[mt][nt][2] = acc[mt][nt][3] = 0.f;
                }
                atomicAdd(&sumsq[lr], s1);
                atomicAdd(&sumsq[lr + 8], s2);
            }
        }
    }

    // rescale own writes
    __syncthreads();
    scale[tid] = 1.f / fmaxf(sqrtf(sumsq[tid]), 1e-12f);
    __syncthreads();
    #pragma unroll 1
    for (int jt = 0; jt < 8; jt++) {
        #pragma unroll
        for (int mt = 0; mt < 4; mt++) {
            const int lr = Wm + mt * 16 + (l >> 2);
            const float sc1 = scale[lr], sc2 = scale[lr + 8];
            #pragma unroll
            for (int nt = 0; nt < 8; nt++) {
                int gj = jt * 128 + Wn + nt * 8 + 2 * (l & 3);
                float2* p1 = reinterpret_cast<float2*>(outp + (size_t)(i0 + lr) * HS + gj);
                float2* p2 = reinterpret_cast<float2*>(outp + (size_t)(i0 + lr + 8) * HS + gj);
                float2 v1 = *p1, v2 = *p2;
                v1.x *= sc1; v1.y *= sc1; v2.x *= sc2; v2.y *= sc2;
                *p1 = v1; *p2 = v2;
            }
        }
    }
}

// ---------------------------------------------------------------------------
extern "C" void kernel_launch(void* const* d_in, const int* in_sizes, int n_in,
                              void* d_out, int out_size) {
    const float* x  = (const float*)d_in[0];
    const float* w1 = (const float*)d_in[1];
    const float* b1 = (const float*)d_in[2];
    const float* w2 = (const float*)d_in[3];
    const float* b2 = (const float*)d_in[4];
    float* out = (float*)d_out;

    cudaFuncSetAttribute(proj_kernel, cudaFuncAttributeMaxDynamicSharedMemorySize, PROJ_SMEM);
    cudaFuncSetAttribute(cofe_kernel, cudaFuncAttributeMaxDynamicSharedMemorySize, COFE_SMEM);

    conv_w3<<<dim3((HS * CC) / 256, 2), 256>>>(w1, w2);
    conv_x3<<<dim3(CC / 32, (HW + 31) / 32, BB), dim3(32, 8)>>>(x);
    proj_kernel<<<dim3(HS / 128, (10 * BB * KP) / 128), 256, PROJ_SMEM>>>(b1, b2);
    cofe_kernel<<<dim3(HS / 256, BB * NO), 256, COFE_SMEM>>>(out);
}

// round 6
// speedup vs baseline: 1.3187x; 1.3187x over previous
#include <cuda_runtime.h>
#include <cuda_bf16.h>
#include <cuda_fp16.h>
#include <math.h>
#include <stdint.h>

#define BB 8
#define CC 512
#define HS 1024
#define KP 144
#define NO 9
#define HW 196

// ---------------- scratch (device globals; zero-initialized) ---------------
__device__ __align__(16) __nv_bfloat16 g_x3 [BB * HW * 1536];   // [(b,hw)][1536] = [Xh,Xh,Xl]
__device__ __align__(16) __nv_bfloat16 g_w13[HS * 1536];        // [h][1536]      = [Wh,Wl,Wh]
__device__ __align__(16) __nv_bfloat16 g_w23[HS * 1536];
// fp16 2-term projections: cp2 rows [cph 0..143 | pad | cpl 160..303 | pad]
__device__ __align__(16) __half g_cp2[BB * 320 * HS];           // [b][320][i]
__device__ __align__(16) __half g_sp2[NO * BB * 160 * HS];      // [o*8+b][160][j] rows 144..159 zero

// ---------------- asm helpers ----------------------------------------------
__device__ __forceinline__ uint32_t smem_u32(const void* p) {
    uint32_t a;
    asm("{ .reg .u64 t; cvta.to.shared.u64 t, %1; cvt.u32.u64 %0, t; }" : "=r"(a) : "l"(p));
    return a;
}
__device__ __forceinline__ void cp16(uint32_t s, const void* g) {
    asm volatile("cp.async.cg.shared.global [%0], [%1], 16;" :: "r"(s), "l"(g));
}
__device__ __forceinline__ void cpcommit() { asm volatile("cp.async.commit_group;" ::: "memory"); }
__device__ __forceinline__ void cpwait0() { asm volatile("cp.async.wait_group 0;" ::: "memory"); }
__device__ __forceinline__ void cpwait1() { asm volatile("cp.async.wait_group 1;" ::: "memory"); }

__device__ __forceinline__ void ldsm4(uint32_t* r, uint32_t a) {
    asm volatile("ldmatrix.sync.aligned.m8n8.x4.shared.b16 {%0,%1,%2,%3}, [%4];"
                 : "=r"(r[0]), "=r"(r[1]), "=r"(r[2]), "=r"(r[3]) : "r"(a));
}
__device__ __forceinline__ void ldsm4t(uint32_t* r, uint32_t a) {
    asm volatile("ldmatrix.sync.aligned.m8n8.x4.trans.shared.b16 {%0,%1,%2,%3}, [%4];"
                 : "=r"(r[0]), "=r"(r[1]), "=r"(r[2]), "=r"(r[3]) : "r"(a));
}
__device__ __forceinline__ void mma_bf16(float* c, const uint32_t* a, const uint32_t* b) {
    asm volatile(
        "mma.sync.aligned.m16n8k16.row.col.f32.bf16.bf16.f32 "
        "{%0,%1,%2,%3},{%4,%5,%6,%7},{%8,%9},{%0,%1,%2,%3};"
        : "+f"(c[0]), "+f"(c[1]), "+f"(c[2]), "+f"(c[3])
        : "r"(a[0]), "r"(a[1]), "r"(a[2]), "r"(a[3]), "r"(b[0]), "r"(b[1]));
}
__device__ __forceinline__ void mma_f16(float* c, const uint32_t* a, const uint32_t* b) {
    asm volatile(
        "mma.sync.aligned.m16n8k16.row.col.f32.f16.f16.f32 "
        "{%0,%1,%2,%3},{%4,%5,%6,%7},{%8,%9},{%0,%1,%2,%3};"
        : "+f"(c[0]), "+f"(c[1]), "+f"(c[2]), "+f"(c[3])
        : "r"(a[0]), "r"(a[1]), "r"(a[2]), "r"(a[3]), "r"(b[0]), "r"(b[1]));
}

// ---------------- convert kernels ------------------------------------------
__global__ void conv_w3(const float* __restrict__ w1, const float* __restrict__ w2) {
    int i = blockIdx.x * 256 + threadIdx.x;
    const float* s = blockIdx.y ? w2 : w1;
    __nv_bfloat16* d = blockIdx.y ? g_w23 : g_w13;
    int h = i >> 9, c = i & 511;
    float v = s[i];
    __nv_bfloat16 hv = __float2bfloat16(v);
    __nv_bfloat16 lv = __float2bfloat16(v - __bfloat162float(hv));
    int base = h * 1536 + c;
    d[base] = hv; d[base + 512] = lv; d[base + 1024] = hv;
}

__global__ void conv_x3(const float* __restrict__ x) {
    __shared__ float t[32][33];
    int b = blockIdx.z, hw0 = blockIdx.y * 32, c0 = blockIdx.x * 32;
    for (int i = threadIdx.y; i < 32; i += 8) {
        int hw = hw0 + threadIdx.x;
        t[i][threadIdx.x] = (hw < HW) ? x[((size_t)b * CC + c0 + i) * HW + hw] : 0.f;
    }
    __syncthreads();
    for (int i = threadIdx.y; i < 32; i += 8) {
        int hw = hw0 + i, c = c0 + threadIdx.x;
        if (hw < HW) {
            float v = t[threadIdx.x][i];
            __nv_bfloat16 hv = __float2bfloat16(v);
            __nv_bfloat16 lv = __float2bfloat16(v - __bfloat162float(hv));
            size_t base = ((size_t)b * HW + hw) * 1536 + c;
            g_x3[base] = hv; g_x3[base + 512] = hv; g_x3[base + 1024] = lv;
        }
    }
}

// ---------------- projection GEMM (bf16 3-term, K'=1536) --------------------
#define PROJ_SMEM 40960
__global__ void __launch_bounds__(256, 2) proj_kernel(const float* __restrict__ b1,
                                                      const float* __restrict__ b2) {
    extern __shared__ char smraw[];
    __shared__ int soff[128];
    __shared__ int doff[128];
    const uint32_t sb = smem_u32(smraw);
    const int tid = threadIdx.x, wid = tid >> 5, l = tid & 31;

    const int h0 = blockIdx.x * 128;
    const int r0 = blockIdx.y * 128;
    const int o = r0 / (BB * KP);
    const int rem0 = r0 - o * (BB * KP);
    const int dy = (o == NO) ? 0 : (o / 3 - 1);
    const int dx = (o == NO) ? 0 : (o % 3 - 1);

    if (tid < 128) {
        int rr = rem0 + tid;
        int b = rr / KP, k = rr - b * KP;
        int yy = 1 + k / 12 + dy, xx = 1 + k % 12 + dx;
        soff[tid] = (b * HW + yy * 14 + xx) * 1536;
        doff[tid] = (((o == NO) ? (b * 320) : ((o * BB + b) * 160)) + k) * 1024;
    }
    const __nv_bfloat16* W = (o == NO) ? g_w13 : g_w23;
    const float* bias = (o == NO) ? b1 : b2;
    __syncthreads();

    const uint32_t Ab[2] = {sb, sb + 10240};
    const uint32_t Bb[2] = {sb + 20480, sb + 30720};

    const int Wm = (wid >> 1) * 32, Wn = (wid & 1) * 64;
    const int aRow = (l & 15), aKb = (l >> 4) * 16;
    const int bN = (l & 7) + (l >> 4) * 8, bKb = ((l >> 3) & 1) * 16;

    float acc[2][8][4] = {};

    {
        #pragma unroll
        for (int i = 0; i < 2; i++) {
            int c = tid + i * 256, row = c >> 2, kc = c & 3;
            cp16(Ab[0] + row * 80 + kc * 16, g_x3 + soff[row] + kc * 8);
        }
        #pragma unroll
        for (int i = 0; i < 2; i++) {
            int c = tid + i * 256, row = c >> 2, kc = c & 3;
            cp16(Bb[0] + row * 80 + kc * 16, W + (size_t)(h0 + row) * 1536 + kc * 8);
        }
        cpcommit();
    }

    for (int it = 0; it < 48; ++it) {
        const int buf = it & 1;
        if (it + 1 < 48) {
            const int c0 = (it + 1) * 32, nb = buf ^ 1;
            #pragma unroll
            for (int i = 0; i < 2; i++) {
                int c = tid + i * 256, row = c >> 2, kc = c & 3;
                cp16(Ab[nb] + row * 80 + kc * 16, g_x3 + soff[row] + c0 + kc * 8);
            }
            #pragma unroll
            for (int i = 0; i < 2; i++) {
                int c = tid + i * 256, row = c >> 2, kc = c & 3;
                cp16(Bb[nb] + row * 80 + kc * 16, W + (size_t)(h0 + row) * 1536 + c0 + kc * 8);
            }
            cpcommit();
            cpwait1();
        } else {
            cpwait0();
        }
        __syncthreads();
        #pragma unroll
        for (int s = 0; s < 2; s++) {
            uint32_t a[2][4], bb[4][4];
            #pragma unroll
            for (int t = 0; t < 2; t++)
                ldsm4(a[t], Ab[buf] + (Wm + t * 16 + aRow) * 80 + s * 32 + aKb);
            #pragma unroll
            for (int p = 0; p < 4; p++)
                ldsm4(bb[p], Bb[buf] + (Wn + p * 16 + bN) * 80 + s * 32 + bKb);
            #pragma unroll
            for (int mt = 0; mt < 2; mt++)
                #pragma unroll
                for (int nt = 0; nt < 8; nt++)
                    mma_bf16(acc[mt][nt], a[mt], &bb[nt >> 1][(nt & 1) * 2]);
        }
        __syncthreads();
    }

    // epilogue: stage, add bias, fp16 split, store (cp: hi+lo; sp: hi only)
    float* stage = (float*)smraw;
    for (int half = 0; half < 2; ++half) {
        __syncthreads();
        if ((wid >> 2) == half) {
            int rbase = Wm - half * 64;
            #pragma unroll
            for (int mt = 0; mt < 2; mt++)
                #pragma unroll
                for (int nt = 0; nt < 8; nt++) {
                    int row = rbase + mt * 16 + (l >> 2);
                    int col = Wn + nt * 8 + 2 * (l & 3);
                    stage[row * 132 + col]           = acc[mt][nt][0];
                    stage[row * 132 + col + 1]       = acc[mt][nt][1];
                    stage[(row + 8) * 132 + col]     = acc[mt][nt][2];
                    stage[(row + 8) * 132 + col + 1] = acc[mt][nt][3];
                }
        }
        __syncthreads();
        for (int idx = tid; idx < 8192; idx += 256) {
            int m = idx >> 7, h = idx & 127;
            float v = stage[m * 132 + h] + bias[h0 + h];
            __half hv = __float2half_rn(v);
            int dbase = doff[half * 64 + m] + h0 + h;
            if (o == NO) {
                __half lv = __float2half_rn(v - __half2float(hv));
                g_cp2[dbase] = hv;
                g_cp2[dbase + 160 * 1024] = lv;
            } else {
                g_sp2[dbase] = hv;
            }
        }
    }
}

// ---------------- cofe GEMM (fp16, K'=320, B reused by both A halves) -------
// C[i][j] = sum_k (cph+cpl)[k][i] * sph[k][j]; BM=256, BN=128, 5 k-tiles of 32
// smem per buf: A0 [32][528B] + A1 [32][528B] + B [32][272B] = 42496; x2 = 84992
#define COFE_SMEM 84992
__global__ void __launch_bounds__(256, 1) cofe_kernel(float* __restrict__ out) {
    extern __shared__ char smraw[];
    const uint32_t sb = smem_u32(smraw);
    const int tid = threadIdx.x, wid = tid >> 5, l = tid & 31;
    const int j0 = blockIdx.x * 128, i0 = blockIdx.y * 256;
    const int p = blockIdx.z, b = p / NO, o = p - b * NO;

    const __half* A0g = g_cp2 + (size_t)b * 320 * 1024 + i0;            // hi rows
    const __half* A1g = A0g + (size_t)160 * 1024;                       // lo rows
    const __half* Bg  = g_sp2 + (size_t)(o * BB + b) * 160 * 1024 + j0;

    const uint32_t AB0[2] = {sb, sb + 42496};                  // A half0
    const uint32_t AB1[2] = {sb + 16896, sb + 42496 + 16896};  // A half1
    const uint32_t BBF[2] = {sb + 33792, sb + 42496 + 33792};  // B

    const int Wm = (wid >> 1) * 64, Wn = (wid & 1) * 64;
    const int aK = (l & 7) + (l >> 4) * 8, aI = ((l >> 3) & 1) * 8;
    const int bK = (l & 7) + ((l >> 3) & 1) * 8, bJ = (l >> 4) * 8;

    float acc[4][8][4] = {};

    // prologue: k-tile 0 into buf 0
    {
        #pragma unroll
        for (int i = 0; i < 4; i++) {
            int c = tid + i * 256, k = c >> 5, ic = c & 31;
            cp16(AB0[0] + k * 528 + ic * 16, A0g + (size_t)k * 1024 + ic * 8);
            cp16(AB1[0] + k * 528 + ic * 16, A1g + (size_t)k * 1024 + ic * 8);
        }
        #pragma unroll
        for (int i = 0; i < 2; i++) {
            int c = tid + i * 256, k = c >> 4, jc = c & 15;
            cp16(BBF[0] + k * 272 + jc * 16, Bg + (size_t)k * 1024 + jc * 8);
        }
        cpcommit();
    }

    for (int it = 0; it < 5; ++it) {
        const int buf = it & 1;
        if (it + 1 < 5) {
            const int k0 = (it + 1) * 32, nb = buf ^ 1;
            #pragma unroll
            for (int i = 0; i < 4; i++) {
                int c = tid + i * 256, k = c >> 5, ic = c & 31;
                cp16(AB0[nb] + k * 528 + ic * 16, A0g + (size_t)(k0 + k) * 1024 + ic * 8);
                cp16(AB1[nb] + k * 528 + ic * 16, A1g + (size_t)(k0 + k) * 1024 + ic * 8);
            }
            #pragma unroll
            for (int i = 0; i < 2; i++) {
                int c = tid + i * 256, k = c >> 4, jc = c & 15;
                cp16(BBF[nb] + k * 272 + jc * 16, Bg + (size_t)(k0 + k) * 1024 + jc * 8);
            }
            cpcommit();
            cpwait1();
        } else {
            cpwait0();
        }
        __syncthreads();
        #pragma unroll
        for (int s = 0; s < 2; s++) {
            uint32_t bb[4][4];
            #pragma unroll
            for (int q = 0; q < 4; q++)
                ldsm4t(bb[q], BBF[buf] + (s * 16 + bK) * 272 + (Wn + q * 16 + bJ) * 2);
            #pragma unroll
            for (int half = 0; half < 2; half++) {
                uint32_t a[4][4];
                const uint32_t Abase = half ? AB1[buf] : AB0[buf];
                #pragma unroll
                for (int t = 0; t < 4; t++)
                    ldsm4t(a[t], Abase + (s * 16 + aK) * 528 + (Wm + t * 16 + aI) * 2);
                #pragma unroll
                for (int mt = 0; mt < 4; mt++)
                    #pragma unroll
                    for (int nt = 0; nt < 8; nt++)
                        mma_f16(acc[mt][nt], a[mt], &bb[nt >> 1][(nt & 1) * 2]);
            }
        }
        __syncthreads();
    }

    float* outp = out + (size_t)p * HS * HS;
    #pragma unroll
    for (int mt = 0; mt < 4; mt++) {
        int gi = i0 + Wm + mt * 16 + (l >> 2);
        #pragma unroll
        for (int nt = 0; nt < 8; nt++) {
            int gj = j0 + Wn + nt * 8 + 2 * (l & 3);
            *reinterpret_cast<float2*>(outp + (size_t)gi * HS + gj) =
                make_float2(acc[mt][nt][0], acc[mt][nt][1]);
            *reinterpret_cast<float2*>(outp + (size_t)(gi + 8) * HS + gj) =
                make_float2(acc[mt][nt][2], acc[mt][nt][3]);
        }
    }
}

// ---------------- row normalize --------------------------------------------
__global__ void norm_kernel(float* __restrict__ out) {
    __shared__ float ws[8];
    __shared__ float sc;
    const size_t row = blockIdx.x;
    float4* p = reinterpret_cast<float4*>(out + row * HS);
    float4 v = p[threadIdx.x];
    float s = v.x * v.x + v.y * v.y + v.z * v.z + v.w * v.w;
    #pragma unroll
    for (int off = 16; off > 0; off >>= 1)
        s += __shfl_xor_sync(0xffffffffu, s, off);
    if ((threadIdx.x & 31) == 0) ws[threadIdx.x >> 5] = s;
    __syncthreads();
    if (threadIdx.x == 0) {
        float t = 0.f;
        #pragma unroll
        for (int i = 0; i < 8; i++) t += ws[i];
        sc = 1.0f / fmaxf(sqrtf(t), 1e-12f);
    }
    __syncthreads();
    float scale = sc;
    v.x *= scale; v.y *= scale; v.z *= scale; v.w *= scale;
    p[threadIdx.x] = v;
}

// ---------------------------------------------------------------------------
extern "C" void kernel_launch(void* const* d_in, const int* in_sizes, int n_in,
                              void* d_out, int out_size) {
    const float* x  = (const float*)d_in[0];
    const float* w1 = (const float*)d_in[1];
    const float* b1 = (const float*)d_in[2];
    const float* w2 = (const float*)d_in[3];
    const float* b2 = (const float*)d_in[4];
    float* out = (float*)d_out;

    cudaFuncSetAttribute(proj_kernel, cudaFuncAttributeMaxDynamicSharedMemorySize, PROJ_SMEM);
    cudaFuncSetAttribute(cofe_kernel, cudaFuncAttributeMaxDynamicSharedMemorySize, COFE_SMEM);

    conv_w3<<<dim3((HS * CC) / 256, 2), 256>>>(w1, w2);
    conv_x3<<<dim3(CC / 32, (HW + 31) / 32, BB), dim3(32, 8)>>>(x);
    proj_kernel<<<dim3(HS / 128, (10 * BB * KP) / 128), 256, PROJ_SMEM>>>(b1, b2);
    cofe_kernel<<<dim3(HS / 128, HS / 256, BB * NO), 256, COFE_SMEM>>>(out);
    norm_kernel<<<BB * NO * HS, 256>>>(out);
}

// round 7
// speedup vs baseline: 1.5101x; 1.1451x over previous
#include <cuda_runtime.h>
#include <cuda_fp16.h>
#include <math.h>
#include <stdint.h>

#define BB 8
#define CC 512
#define HS 1024
#define KP 144
#define NO 9
#define HW 196

// ---------------- scratch (device globals; zero-initialized) ---------------
__device__ __align__(16) __half g_x2 [BB * HW * 1024];   // [(b,hw)][1024] = [Xh, Xh]
__device__ __align__(16) __half g_w12[HS * 1024];        // [h][1024]      = [Wh | Wl]
__device__ __align__(16) __half g_w22[HS * 1024];
// fp16 2-term projections: cp2 rows [cph 0..143 | pad | cpl 160..303 | pad]
__device__ __align__(16) __half g_cp2[BB * 320 * HS];    // [b][320][i]
__device__ __align__(16) __half g_sp2[NO * BB * 160 * HS]; // [o*8+b][160][j] rows 144..159 zero

// ---------------- asm helpers ----------------------------------------------
__device__ __forceinline__ uint32_t smem_u32(const void* p) {
    uint32_t a;
    asm("{ .reg .u64 t; cvta.to.shared.u64 t, %1; cvt.u32.u64 %0, t; }" : "=r"(a) : "l"(p));
    return a;
}
__device__ __forceinline__ void cp16(uint32_t s, const void* g) {
    asm volatile("cp.async.cg.shared.global [%0], [%1], 16;" :: "r"(s), "l"(g));
}
__device__ __forceinline__ void cpcommit() { asm volatile("cp.async.commit_group;" ::: "memory"); }
__device__ __forceinline__ void cpwait0() { asm volatile("cp.async.wait_group 0;" ::: "memory"); }
__device__ __forceinline__ void cpwait1() { asm volatile("cp.async.wait_group 1;" ::: "memory"); }

__device__ __forceinline__ void ldsm4(uint32_t* r, uint32_t a) {
    asm volatile("ldmatrix.sync.aligned.m8n8.x4.shared.b16 {%0,%1,%2,%3}, [%4];"
                 : "=r"(r[0]), "=r"(r[1]), "=r"(r[2]), "=r"(r[3]) : "r"(a));
}
__device__ __forceinline__ void ldsm4t(uint32_t* r, uint32_t a) {
    asm volatile("ldmatrix.sync.aligned.m8n8.x4.trans.shared.b16 {%0,%1,%2,%3}, [%4];"
                 : "=r"(r[0]), "=r"(r[1]), "=r"(r[2]), "=r"(r[3]) : "r"(a));
}
__device__ __forceinline__ void mma_f16(float* c, const uint32_t* a, const uint32_t* b) {
    asm volatile(
        "mma.sync.aligned.m16n8k16.row.col.f32.f16.f16.f32 "
        "{%0,%1,%2,%3},{%4,%5,%6,%7},{%8,%9},{%0,%1,%2,%3};"
        : "+f"(c[0]), "+f"(c[1]), "+f"(c[2]), "+f"(c[3])
        : "r"(a[0]), "r"(a[1]), "r"(a[2]), "r"(a[3]), "r"(b[0]), "r"(b[1]));
}

// ---------------- convert kernels ------------------------------------------
__global__ void conv_w2(const float* __restrict__ w1, const float* __restrict__ w2) {
    int i = blockIdx.x * 256 + threadIdx.x;
    const float* s = blockIdx.y ? w2 : w1;
    __half* d = blockIdx.y ? g_w22 : g_w12;
    int h = i >> 9, c = i & 511;
    float v = s[i];
    __half hv = __float2half_rn(v);
    __half lv = __float2half_rn(v - __half2float(hv));
    int base = h * 1024 + c;
    d[base] = hv; d[base + 512] = lv;
}

__global__ void conv_x2(const float* __restrict__ x) {
    __shared__ float t[32][33];
    int b = blockIdx.z, hw0 = blockIdx.y * 32, c0 = blockIdx.x * 32;
    for (int i = threadIdx.y; i < 32; i += 8) {
        int hw = hw0 + threadIdx.x;
        t[i][threadIdx.x] = (hw < HW) ? x[((size_t)b * CC + c0 + i) * HW + hw] : 0.f;
    }
    __syncthreads();
    for (int i = threadIdx.y; i < 32; i += 8) {
        int hw = hw0 + i, c = c0 + threadIdx.x;
        if (hw < HW) {
            __half hv = __float2half_rn(t[threadIdx.x][i]);
            size_t base = ((size_t)b * HW + hw) * 1024 + c;
            g_x2[base] = hv; g_x2[base + 512] = hv;
        }
    }
}

// ---------------- projection GEMM (fp16 2-term, K'=1024) --------------------
// D[row][h] = sum_k' X2[row][k'] * W2[h][k'] = (Wh+Wl)·Xh
#define PROJ_SMEM 40960
__global__ void __launch_bounds__(256, 2) proj_kernel(const float* __restrict__ b1,
                                                      const float* __restrict__ b2) {
    extern __shared__ char smraw[];
    __shared__ int soff[128];
    __shared__ int doff[128];
    const uint32_t sb = smem_u32(smraw);
    const int tid = threadIdx.x, wid = tid >> 5, l = tid & 31;

    const int h0 = blockIdx.x * 128;
    const int r0 = blockIdx.y * 128;
    const int o = r0 / (BB * KP);
    const int rem0 = r0 - o * (BB * KP);
    const int dy = (o == NO) ? 0 : (o / 3 - 1);
    const int dx = (o == NO) ? 0 : (o % 3 - 1);

    if (tid < 128) {
        int rr = rem0 + tid;
        int b = rr / KP, k = rr - b * KP;
        int yy = 1 + k / 12 + dy, xx = 1 + k % 12 + dx;
        soff[tid] = (b * HW + yy * 14 + xx) * 1024;
        doff[tid] = (((o == NO) ? (b * 320) : ((o * BB + b) * 160)) + k) * 1024;
    }
    const __half* W = (o == NO) ? g_w12 : g_w22;
    const float* bias = (o == NO) ? b1 : b2;
    __syncthreads();

    const uint32_t Ab[2] = {sb, sb + 10240};
    const uint32_t Bb[2] = {sb + 20480, sb + 30720};

    const int Wm = (wid >> 1) * 32, Wn = (wid & 1) * 64;
    const int aRow = (l & 15), aKb = (l >> 4) * 16;
    const int bN = (l & 7) + (l >> 4) * 8, bKb = ((l >> 3) & 1) * 16;

    float acc[2][8][4] = {};

    {
        #pragma unroll
        for (int i = 0; i < 2; i++) {
            int c = tid + i * 256, row = c >> 2, kc = c & 3;
            cp16(Ab[0] + row * 80 + kc * 16, g_x2 + soff[row] + kc * 8);
        }
        #pragma unroll
        for (int i = 0; i < 2; i++) {
            int c = tid + i * 256, row = c >> 2, kc = c & 3;
            cp16(Bb[0] + row * 80 + kc * 16, W + (size_t)(h0 + row) * 1024 + kc * 8);
        }
        cpcommit();
    }

    for (int it = 0; it < 32; ++it) {
        const int buf = it & 1;
        if (it + 1 < 32) {
            const int c0 = (it + 1) * 32, nb = buf ^ 1;
            #pragma unroll
            for (int i = 0; i < 2; i++) {
                int c = tid + i * 256, row = c >> 2, kc = c & 3;
                cp16(Ab[nb] + row * 80 + kc * 16, g_x2 + soff[row] + c0 + kc * 8);
            }
            #pragma unroll
            for (int i = 0; i < 2; i++) {
                int c = tid + i * 256, row = c >> 2, kc = c & 3;
                cp16(Bb[nb] + row * 80 + kc * 16, W + (size_t)(h0 + row) * 1024 + c0 + kc * 8);
            }
            cpcommit();
            cpwait1();
        } else {
            cpwait0();
        }
        __syncthreads();
        #pragma unroll
        for (int s = 0; s < 2; s++) {
            uint32_t a[2][4], bb[4][4];
            #pragma unroll
            for (int t = 0; t < 2; t++)
                ldsm4(a[t], Ab[buf] + (Wm + t * 16 + aRow) * 80 + s * 32 + aKb);
            #pragma unroll
            for (int p = 0; p < 4; p++)
                ldsm4(bb[p], Bb[buf] + (Wn + p * 16 + bN) * 80 + s * 32 + bKb);
            #pragma unroll
            for (int mt = 0; mt < 2; mt++)
                #pragma unroll
                for (int nt = 0; nt < 8; nt++)
                    mma_f16(acc[mt][nt], a[mt], &bb[nt >> 1][(nt & 1) * 2]);
        }
        __syncthreads();
    }

    // epilogue: stage, add bias, fp16 split, store (cp: hi+lo; sp: hi only)
    float* stage = (float*)smraw;
    for (int half = 0; half < 2; ++half) {
        __syncthreads();
        if ((wid >> 2) == half) {
            int rbase = Wm - half * 64;
            #pragma unroll
            for (int mt = 0; mt < 2; mt++)
                #pragma unroll
                for (int nt = 0; nt < 8; nt++) {
                    int row = rbase + mt * 16 + (l >> 2);
                    int col = Wn + nt * 8 + 2 * (l & 3);
                    stage[row * 132 + col]           = acc[mt][nt][0];
                    stage[row * 132 + col + 1]       = acc[mt][nt][1];
                    stage[(row + 8) * 132 + col]     = acc[mt][nt][2];
                    stage[(row + 8) * 132 + col + 1] = acc[mt][nt][3];
                }
        }
        __syncthreads();
        for (int idx = tid; idx < 8192; idx += 256) {
            int m = idx >> 7, h = idx & 127;
            float v = stage[m * 132 + h] + bias[h0 + h];
            __half hv = __float2half_rn(v);
            int dbase = doff[half * 64 + m] + h0 + h;
            if (o == NO) {
                __half lv = __float2half_rn(v - __half2float(hv));
                g_cp2[dbase] = hv;
                g_cp2[dbase + 160 * 1024] = lv;
            } else {
                g_sp2[dbase] = hv;
            }
        }
    }
}

// ---------------- cofe GEMM (fp16, K=144 effective, B reused) ---------------
// C[i][j] = sum_k (cph+cpl)[k][i] * sph[k][j]; last k-tile half (pad skip)
#define COFE_SMEM 84992
__global__ void __launch_bounds__(256, 1) cofe_kernel(float* __restrict__ out) {
    extern __shared__ char smraw[];
    const uint32_t sb = smem_u32(smraw);
    const int tid = threadIdx.x, wid = tid >> 5, l = tid & 31;
    const int j0 = blockIdx.x * 128, i0 = blockIdx.y * 256;
    const int p = blockIdx.z, b = p / NO, o = p - b * NO;

    const __half* A0g = g_cp2 + (size_t)b * 320 * 1024 + i0;
    const __half* A1g = A0g + (size_t)160 * 1024;
    const __half* Bg  = g_sp2 + (size_t)(o * BB + b) * 160 * 1024 + j0;

    const uint32_t AB0[2] = {sb, sb + 42496};
    const uint32_t AB1[2] = {sb + 16896, sb + 42496 + 16896};
    const uint32_t BBF[2] = {sb + 33792, sb + 42496 + 33792};

    const int Wm = (wid >> 1) * 64, Wn = (wid & 1) * 64;
    const int aK = (l & 7) + (l >> 4) * 8, aI = ((l >> 3) & 1) * 8;
    const int bK = (l & 7) + ((l >> 3) & 1) * 8, bJ = (l >> 4) * 8;

    float acc[4][8][4] = {};

    {
        #pragma unroll
        for (int i = 0; i < 4; i++) {
            int c = tid + i * 256, k = c >> 5, ic = c & 31;
            cp16(AB0[0] + k * 528 + ic * 16, A0g + (size_t)k * 1024 + ic * 8);
            cp16(AB1[0] + k * 528 + ic * 16, A1g + (size_t)k * 1024 + ic * 8);
        }
        #pragma unroll
        for (int i = 0; i < 2; i++) {
            int c = tid + i * 256, k = c >> 4, jc = c & 15;
            cp16(BBF[0] + k * 272 + jc * 16, Bg + (size_t)k * 1024 + jc * 8);
        }
        cpcommit();
    }

    for (int it = 0; it < 5; ++it) {
        const int buf = it & 1;
        if (it + 1 < 5) {
            const int k0 = (it + 1) * 32, nb = buf ^ 1;
            #pragma unroll
            for (int i = 0; i < 4; i++) {
                int c = tid + i * 256, k = c >> 5, ic = c & 31;
                cp16(AB0[nb] + k * 528 + ic * 16, A0g + (size_t)(k0 + k) * 1024 + ic * 8);
                cp16(AB1[nb] + k * 528 + ic * 16, A1g + (size_t)(k0 + k) * 1024 + ic * 8);
            }
            #pragma unroll
            for (int i = 0; i < 2; i++) {
                int c = tid + i * 256, k = c >> 4, jc = c & 15;
                cp16(BBF[nb] + k * 272 + jc * 16, Bg + (size_t)(k0 + k) * 1024 + jc * 8);
            }
            cpcommit();
            cpwait1();
        } else {
            cpwait0();
        }
        __syncthreads();
        #pragma unroll
        for (int s = 0; s < 2; s++) {
            if (s == 1 && it == 4) break;   // rows 144..159 are zero pad
            uint32_t bb[4][4];
            #pragma unroll
            for (int q = 0; q < 4; q++)
                ldsm4t(bb[q], BBF[buf] + (s * 16 + bK) * 272 + (Wn + q * 16 + bJ) * 2);
            #pragma unroll
            for (int half = 0; half < 2; half++) {
                uint32_t a[4][4];
                const uint32_t Abase = half ? AB1[buf] : AB0[buf];
                #pragma unroll
                for (int t = 0; t < 4; t++)
                    ldsm4t(a[t], Abase + (s * 16 + aK) * 528 + (Wm + t * 16 + aI) * 2);
                #pragma unroll
                for (int mt = 0; mt < 4; mt++)
                    #pragma unroll
                    for (int nt = 0; nt < 8; nt++)
                        mma_f16(acc[mt][nt], a[mt], &bb[nt >> 1][(nt & 1) * 2]);
            }
        }
        __syncthreads();
    }

    float* outp = out + (size_t)p * HS * HS;
    #pragma unroll
    for (int mt = 0; mt < 4; mt++) {
        int gi = i0 + Wm + mt * 16 + (l >> 2);
        #pragma unroll
        for (int nt = 0; nt < 8; nt++) {
            int gj = j0 + Wn + nt * 8 + 2 * (l & 3);
            *reinterpret_cast<float2*>(outp + (size_t)gi * HS + gj) =
                make_float2(acc[mt][nt][0], acc[mt][nt][1]);
            *reinterpret_cast<float2*>(outp + (size_t)(gi + 8) * HS + gj) =
                make_float2(acc[mt][nt][2], acc[mt][nt][3]);
        }
    }
}

// ---------------- row normalize --------------------------------------------
__global__ void norm_kernel(float* __restrict__ out) {
    __shared__ float ws[8];
    __shared__ float sc;
    const size_t row = blockIdx.x;
    float4* p = reinterpret_cast<float4*>(out + row * HS);
    float4 v = p[threadIdx.x];
    float s = v.x * v.x + v.y * v.y + v.z * v.z + v.w * v.w;
    #pragma unroll
    for (int off = 16; off > 0; off >>= 1)
        s += __shfl_xor_sync(0xffffffffu, s, off);
    if ((threadIdx.x & 31) == 0) ws[threadIdx.x >> 5] = s;
    __syncthreads();
    if (threadIdx.x == 0) {
        float t = 0.f;
        #pragma unroll
        for (int i = 0; i < 8; i++) t += ws[i];
        sc = 1.0f / fmaxf(sqrtf(t), 1e-12f);
    }
    __syncthreads();
    float scale = sc;
    v.x *= scale; v.y *= scale; v.z *= scale; v.w *= scale;
    p[threadIdx.x] = v;
}

// ---------------------------------------------------------------------------
extern "C" void kernel_launch(void* const* d_in, const int* in_sizes, int n_in,
                              void* d_out, int out_size) {
    const float* x  = (const float*)d_in[0];
    const float* w1 = (const float*)d_in[1];
    const float* b1 = (const float*)d_in[2];
    const float* w2 = (const float*)d_in[3];
    const float* b2 = (const float*)d_in[4];
    float* out = (float*)d_out;

    cudaFuncSetAttribute(proj_kernel, cudaFuncAttributeMaxDynamicSharedMemorySize, PROJ_SMEM);
    cudaFuncSetAttribute(cofe_kernel, cudaFuncAttributeMaxDynamicSharedMemorySize, COFE_SMEM);

    conv_w2<<<dim3((HS * CC) / 256, 2), 256>>>(w1, w2);
    conv_x2<<<dim3(CC / 32, (HW + 31) / 32, BB), dim3(32, 8)>>>(x);
    proj_kernel<<<dim3(HS / 128, (10 * BB * KP) / 128), 256, PROJ_SMEM>>>(b1, b2);
    cofe_kernel<<<dim3(HS / 128, HS / 256, BB * NO), 256, COFE_SMEM>>>(out);
    norm_kernel<<<BB * NO * HS, 256>>>(out);
}